// round 16
// baseline (speedup 1.0000x reference)
#include <cuda_runtime.h>
#include <math_constants.h>

static constexpr int NPTS  = 4096;
static constexpr int NUP   = 16384;
static constexpr int BATCH = 4;
static constexpr int C     = 64;

static constexpr int S      = 2;            // point slices (bigger slice = fewer warm-up fires)
static constexpr int SLICE  = NPTS / S;     // 2048 points
static constexpr int TPB_A  = 128;
static constexpr int QA     = 2;            // queries per thread (phase A)
static constexpr int QTILE  = TPB_A * QA;   // 256 queries per block

static constexpr int TPB_B  = 256;          // 8 warps = 8 d-groups
static constexpr int QBLK_B = 128;          // queries per B block (4 per thread)
static constexpr int NFS    = 68;           // nf row stride (floats), padded
static constexpr int SMEM_B = (C * C + C + QBLK_B * 4 * 2 + QBLK_B * NFS) * 4; // 55552

// per-(slice, batch, query) top-3: values and indices (bitcast)
__device__ float4 g_scrV[S * BATCH * NUP];
__device__ float4 g_scrI[S * BATCH * NUP];

// ---- packed f32x2 helpers (Blackwell) ----
__device__ __forceinline__ unsigned long long pk2(float lo, float hi) {
    unsigned long long r;
    asm("mov.b64 %0, {%1, %2};" : "=l"(r) : "f"(lo), "f"(hi));
    return r;
}
__device__ __forceinline__ unsigned long long fma2(unsigned long long a,
                                                   unsigned long long b,
                                                   unsigned long long c) {
    unsigned long long d;
    asm("fma.rn.f32x2 %0, %1, %2, %3;" : "=l"(d) : "l"(a), "l"(b), "l"(c));
    return d;
}
__device__ __forceinline__ void unpk2(unsigned long long v, float& lo, float& hi) {
    asm("mov.b64 {%0, %1}, %2;" : "=f"(lo), "=f"(hi) : "l"(v));
}

// strict-< branchy insert: keeps earliest index on ties (jax.lax.top_k stability)
__device__ __forceinline__ void ins3(float v, int i,
                                     float& v0, float& v1, float& v2,
                                     int& i0, int& i1, int& i2) {
    if (v < v2) {
        if (v < v1) {
            v2 = v1; i2 = i1;
            if (v < v0) { v1 = v0; i1 = i0; v0 = v; i0 = i; }
            else        { v1 = v;  i1 = i; }
        } else { v2 = v; i2 = i; }
    }
}

// ============ Phase A: per-slice top-3, points pair-packed as u64 lanes ======
__global__ void __launch_bounds__(TPB_A, 4)
knn_slice_kernel(const float* __restrict__ pos,
                 const float* __restrict__ pos_up)
{
    // pair p: [2p] = {(x0,x1),(y0,y1)}, [2p+1] = {(z0,z1),(h0,h1)}
    __shared__ ulonglong2 spair[SLICE];    // 32 KB

    const int s   = blockIdx.y;
    const int b   = blockIdx.z;
    const int tid = threadIdx.x;

    {
        const float* pb = pos + ((size_t)b * NPTS + (size_t)s * SLICE) * 3;
        for (int p = tid; p < SLICE / 2; p += TPB_A) {
            const float* s6 = pb + 6 * p;
            float x0 = s6[0], y0 = s6[1], z0 = s6[2];
            float x1 = s6[3], y1 = s6[4], z1 = s6[5];
            ulonglong2 A, B;
            A.x = pk2(x0, x1);
            A.y = pk2(y0, y1);
            B.x = pk2(z0, z1);
            B.y = pk2(0.5f * (x0 * x0 + y0 * y0 + z0 * z0),
                      0.5f * (x1 * x1 + y1 * y1 + z1 * z1));
            spair[2 * p + 0] = A;
            spair[2 * p + 1] = B;
        }
    }
    __syncthreads();

    const int qbase = blockIdx.x * QTILE + tid;

    unsigned long long nx[QA], ny[QA], nz[QA];
    #pragma unroll
    for (int k = 0; k < QA; ++k) {
        const int q = qbase + k * TPB_A;
        const float* pu = pos_up + (size_t)(b * NUP + q) * 3;
        float x = pu[0], y = pu[1], z = pu[2];
        nx[k] = pk2(-x, -x); ny[k] = pk2(-y, -y); nz[k] = pk2(-z, -z);
    }

    float v0[QA], v1[QA], v2[QA];
    int   i0[QA], i1[QA], i2[QA];
    #pragma unroll
    for (int k = 0; k < QA; ++k) {
        v0[k] = v1[k] = v2[k] = CUDART_INF_F;
        i0[k] = i1[k] = i2[k] = 0;
    }

    const int jbase = s * SLICE;

    #pragma unroll 4
    for (int p = 0; p < SLICE / 2; ++p) {
        ulonglong2 A  = spair[2 * p + 0];   // xs, ys (packed point-pairs)
        ulonglong2 Bv = spair[2 * p + 1];   // zs, hs

        #pragma unroll
        for (int k = 0; k < QA; ++k) {
            unsigned long long sP = fma2(A.x, nx[k], Bv.y);
            sP = fma2(A.y, ny[k], sP);
            sP = fma2(Bv.x, nz[k], sP);
            float s0, s1;
            unpk2(sP, s0, s1);
            if (fminf(s0, s1) < v2[k]) {     // per-query gate, branchy inserts
                ins3(s0, jbase + 2 * p,     v0[k], v1[k], v2[k], i0[k], i1[k], i2[k]);
                ins3(s1, jbase + 2 * p + 1, v0[k], v1[k], v2[k], i0[k], i1[k], i2[k]);
            }
        }
    }

    #pragma unroll
    for (int k = 0; k < QA; ++k) {
        const int q = qbase + k * TPB_A;
        const size_t o = ((size_t)s * BATCH + b) * NUP + q;
        g_scrV[o] = make_float4(v0[k], v1[k], v2[k], 0.0f);
        g_scrI[o] = make_float4(__int_as_float(i0[k]), __int_as_float(i1[k]),
                                __int_as_float(i2[k]), 0.0f);
    }
}

// ====== Phase B: merge-once + 8 d-groups x 4 queries/thread, smem W, f32x2 ===
__global__ void __launch_bounds__(TPB_B, 3)
epilogue_kernel(const float* __restrict__ feature,
                const float* __restrict__ pos_up,
                const float* __restrict__ W,
                const float* __restrict__ bias,
                float* __restrict__ out)
{
    extern __shared__ float sm[];
    float* sW  = sm;                         // [4096]  row c = 64 floats
    float* sb  = sW + C * C;                 // [64]
    float* sWT = sb + C;                     // [128*4] w0,w1,w2,_
    float* sID = sWT + QBLK_B * 4;           // [128*4] i0,i1,i2,_ (bitcast int)
    float* snf = sID + QBLK_B * 4;           // [128*NFS]

    const int b    = blockIdx.y;
    const int tid  = threadIdx.x;
    const int w    = tid >> 5;               // d-group: outputs [8w, 8w+8)
    const int lane = tid & 31;
    const int qb   = blockIdx.x * QBLK_B;

    // ---- stage 1: threads 0-127 merge one query each; 128-255 stage W/b ----
    if (tid < QBLK_B) {
        const int q = qb + tid;
        float v0 = CUDART_INF_F, v1 = CUDART_INF_F, v2 = CUDART_INF_F;
        int   i0 = 0, i1 = 0, i2 = 0;
        #pragma unroll
        for (int s = 0; s < S; ++s) {
            const size_t o = ((size_t)s * BATCH + b) * NUP + q;
            float4 vv = g_scrV[o];
            float4 ii = g_scrI[o];
            ins3(vv.x, __float_as_int(ii.x), v0, v1, v2, i0, i1, i2);
            ins3(vv.y, __float_as_int(ii.y), v0, v1, v2, i0, i1, i2);
            ins3(vv.z, __float_as_int(ii.z), v0, v1, v2, i0, i1, i2);
        }
        const float* pu = pos_up + (size_t)(b * NUP + q) * 3;
        const float pux = pu[0], puy = pu[1], puz = pu[2];
        const float nu  = pux * pux + puy * puy + puz * puz;
        float w0 = 1.0f / (__fmaf_rn(2.0f, v0, nu) + 1e-6f);
        float w1 = 1.0f / (__fmaf_rn(2.0f, v1, nu) + 1e-6f);
        float w2 = 1.0f / (__fmaf_rn(2.0f, v2, nu) + 1e-6f);
        float inv = 1.0f / (w0 + w1 + w2);
        reinterpret_cast<float4*>(sWT)[tid] = make_float4(w0 * inv, w1 * inv, w2 * inv, 0.0f);
        reinterpret_cast<float4*>(sID)[tid] = make_float4(__int_as_float(i0), __int_as_float(i1),
                                                          __int_as_float(i2), 0.0f);
    } else {
        const int t = tid - QBLK_B;
        const float4* Wg = reinterpret_cast<const float4*>(W);
        float4*       Ws = reinterpret_cast<float4*>(sW);
        #pragma unroll
        for (int i = t; i < C * C / 4; i += QBLK_B) Ws[i] = Wg[i];
        if (t < C / 4)
            reinterpret_cast<float4*>(sb)[t] = reinterpret_cast<const float4*>(bias)[t];
    }
    __syncthreads();

    // ---- stage 2: nf for channels [8w, 8w+8) of 4 queries -> padded smem ----
    #pragma unroll
    for (int k = 0; k < 4; ++k) {
        const int qloc = k * 32 + lane;
        float4 wt = reinterpret_cast<const float4*>(sWT)[qloc];
        float4 id = reinterpret_cast<const float4*>(sID)[qloc];
        const int i0 = __float_as_int(id.x);
        const int i1 = __float_as_int(id.y);
        const int i2 = __float_as_int(id.z);

        const float4* f0 = reinterpret_cast<const float4*>(feature + (size_t)(b * NPTS + i0) * C) + 2 * w;
        const float4* f1 = reinterpret_cast<const float4*>(feature + (size_t)(b * NPTS + i1) * C) + 2 * w;
        const float4* f2 = reinterpret_cast<const float4*>(feature + (size_t)(b * NPTS + i2) * C) + 2 * w;
        float4* dst = reinterpret_cast<float4*>(snf + qloc * NFS + 8 * w);
        #pragma unroll
        for (int i = 0; i < 2; ++i) {
            float4 a = __ldg(f0 + i);
            float4 e = __ldg(f1 + i);
            float4 g = __ldg(f2 + i);
            float4 nf;
            nf.x = __fmaf_rn(wt.x, a.x, __fmaf_rn(wt.y, e.x, wt.z * g.x));
            nf.y = __fmaf_rn(wt.x, a.y, __fmaf_rn(wt.y, e.y, wt.z * g.y));
            nf.z = __fmaf_rn(wt.x, a.z, __fmaf_rn(wt.y, e.z, wt.z * g.z));
            nf.w = __fmaf_rn(wt.x, a.w, __fmaf_rn(wt.y, e.w, wt.z * g.w));
            dst[i] = nf;
        }
    }
    __syncthreads();

    // ---- stage 3: GEMM, 4 queries x 8 outputs (4 packed d-pairs each) ----
    const ulonglong2* sW2 = reinterpret_cast<const ulonglong2*>(sW);  // row c = 16 u2

    unsigned long long acc2[4][4];
    {
        const unsigned long long* sb1 = reinterpret_cast<const unsigned long long*>(sb);
        unsigned long long b0 = sb1[4 * w + 0], b1 = sb1[4 * w + 1];
        unsigned long long b2 = sb1[4 * w + 2], b3 = sb1[4 * w + 3];
        #pragma unroll
        for (int k = 0; k < 4; ++k) {
            acc2[k][0] = b0; acc2[k][1] = b1; acc2[k][2] = b2; acc2[k][3] = b3;
        }
    }

    #pragma unroll 4
    for (int c4 = 0; c4 < 16; ++c4) {
        float4 nf4[4];
        #pragma unroll
        for (int k = 0; k < 4; ++k)
            nf4[k] = *reinterpret_cast<const float4*>(snf + (k * 32 + lane) * NFS + 4 * c4);

        #pragma unroll
        for (int kk = 0; kk < 4; ++kk) {
            const int c = 4 * c4 + kk;
            ulonglong2 wa = sW2[(size_t)c * 16 + 2 * w + 0];   // LDS.128 broadcast
            ulonglong2 wb = sW2[(size_t)c * 16 + 2 * w + 1];
            #pragma unroll
            for (int k = 0; k < 4; ++k) {
                const float nfv = kk == 0 ? nf4[k].x : kk == 1 ? nf4[k].y
                                 : kk == 2 ? nf4[k].z : nf4[k].w;
                const unsigned long long nf2 = pk2(nfv, nfv);
                acc2[k][0] = fma2(nf2, wa.x, acc2[k][0]);
                acc2[k][1] = fma2(nf2, wa.y, acc2[k][1]);
                acc2[k][2] = fma2(nf2, wb.x, acc2[k][2]);
                acc2[k][3] = fma2(nf2, wb.y, acc2[k][3]);
            }
        }
    }

    // ---- ReLU + store: each query's d-segment [8w, 8w+8) ----
    #pragma unroll
    for (int k = 0; k < 4; ++k) {
        const int q = qb + k * 32 + lane;
        float4* o4 = reinterpret_cast<float4*>(out + (size_t)(b * NUP + q) * C + 8 * w);
        float x0, x1, x2, x3;
        unpk2(acc2[k][0], x0, x1);
        unpk2(acc2[k][1], x2, x3);
        o4[0] = make_float4(fmaxf(x0, 0.0f), fmaxf(x1, 0.0f), fmaxf(x2, 0.0f), fmaxf(x3, 0.0f));
        unpk2(acc2[k][2], x0, x1);
        unpk2(acc2[k][3], x2, x3);
        o4[1] = make_float4(fmaxf(x0, 0.0f), fmaxf(x1, 0.0f), fmaxf(x2, 0.0f), fmaxf(x3, 0.0f));
    }
}

extern "C" void kernel_launch(void* const* d_in, const int* in_sizes, int n_in,
                              void* d_out, int out_size)
{
    const float* feature = (const float*)d_in[0];
    const float* pos     = (const float*)d_in[1];
    const float* pos_up  = (const float*)d_in[2];
    const float* W       = (const float*)d_in[3];
    const float* bias    = (const float*)d_in[4];
    float* out = (float*)d_out;

    cudaFuncSetAttribute(epilogue_kernel, cudaFuncAttributeMaxDynamicSharedMemorySize, SMEM_B);

    dim3 gridA(NUP / QTILE, S, BATCH);      // (64, 2, 4) = 512 blocks
    knn_slice_kernel<<<gridA, TPB_A>>>(pos, pos_up);

    dim3 gridB(NUP / QBLK_B, BATCH);        // (128, 4) = 512 blocks
    epilogue_kernel<<<gridB, TPB_B, SMEM_B>>>(feature, pos_up, W, bias, out);
}

// round 17
// speedup vs baseline: 1.2248x; 1.2248x over previous
#include <cuda_runtime.h>
#include <math_constants.h>

static constexpr int NPTS  = 4096;
static constexpr int NUP   = 16384;
static constexpr int BATCH = 4;
static constexpr int C     = 64;

static constexpr int S      = 4;            // point slices (measured best)
static constexpr int SLICE  = NPTS / S;     // 1024 points
static constexpr int TPB_A  = 128;
static constexpr int QA     = 2;            // queries per thread (phase A)
static constexpr int QTILE  = TPB_A * QA;   // 256 queries per block

static constexpr int TPB_B  = 256;          // 8 warps = 8 d-groups
static constexpr int QBLK_B = 64;           // queries per B block (2 per thread)
static constexpr int NFS    = 68;           // nf row stride (floats), padded
// smem: W[4096] + b[64] + wt[64*4] + id[64*4] + snf[64*68]  = 36096 B
static constexpr int SMEM_B = (C * C + C + QBLK_B * 4 * 2 + QBLK_B * NFS) * 4;

// per-(slice, batch, query) top-3: values and indices (bitcast)
__device__ float4 g_scrV[S * BATCH * NUP];
__device__ float4 g_scrI[S * BATCH * NUP];

// ---- packed f32x2 helpers (Blackwell) ----
__device__ __forceinline__ unsigned long long pk2(float lo, float hi) {
    unsigned long long r;
    asm("mov.b64 %0, {%1, %2};" : "=l"(r) : "f"(lo), "f"(hi));
    return r;
}
__device__ __forceinline__ unsigned long long fma2(unsigned long long a,
                                                   unsigned long long b,
                                                   unsigned long long c) {
    unsigned long long d;
    asm("fma.rn.f32x2 %0, %1, %2, %3;" : "=l"(d) : "l"(a), "l"(b), "l"(c));
    return d;
}
__device__ __forceinline__ void unpk2(unsigned long long v, float& lo, float& hi) {
    asm("mov.b64 {%0, %1}, %2;" : "=f"(lo), "=f"(hi) : "l"(v));
}

// strict-< branchy insert: keeps earliest index on ties (jax.lax.top_k stability)
__device__ __forceinline__ void ins3(float v, int i,
                                     float& v0, float& v1, float& v2,
                                     int& i0, int& i1, int& i2) {
    if (v < v2) {
        if (v < v1) {
            v2 = v1; i2 = i1;
            if (v < v0) { v1 = v0; i1 = i0; v0 = v; i0 = i; }
            else        { v1 = v;  i1 = i; }
        } else { v2 = v; i2 = i; }
    }
}

// ============ Phase A: per-slice top-3, points pair-packed as u64 lanes ======
__global__ void __launch_bounds__(TPB_A, 8)
knn_slice_kernel(const float* __restrict__ pos,
                 const float* __restrict__ pos_up)
{
    // pair p: [2p] = {(x0,x1),(y0,y1)}, [2p+1] = {(z0,z1),(h0,h1)}
    __shared__ ulonglong2 spair[SLICE];

    const int s   = blockIdx.y;
    const int b   = blockIdx.z;
    const int tid = threadIdx.x;

    {
        const float* pb = pos + ((size_t)b * NPTS + (size_t)s * SLICE) * 3;
        for (int p = tid; p < SLICE / 2; p += TPB_A) {
            const float* s6 = pb + 6 * p;
            float x0 = s6[0], y0 = s6[1], z0 = s6[2];
            float x1 = s6[3], y1 = s6[4], z1 = s6[5];
            ulonglong2 A, B;
            A.x = pk2(x0, x1);
            A.y = pk2(y0, y1);
            B.x = pk2(z0, z1);
            B.y = pk2(0.5f * (x0 * x0 + y0 * y0 + z0 * z0),
                      0.5f * (x1 * x1 + y1 * y1 + z1 * z1));
            spair[2 * p + 0] = A;
            spair[2 * p + 1] = B;
        }
    }
    __syncthreads();

    const int qbase = blockIdx.x * QTILE + tid;

    unsigned long long nx[QA], ny[QA], nz[QA];
    #pragma unroll
    for (int k = 0; k < QA; ++k) {
        const int q = qbase + k * TPB_A;
        const float* pu = pos_up + (size_t)(b * NUP + q) * 3;
        float x = pu[0], y = pu[1], z = pu[2];
        nx[k] = pk2(-x, -x); ny[k] = pk2(-y, -y); nz[k] = pk2(-z, -z);
    }

    float v0[QA], v1[QA], v2[QA];
    int   i0[QA], i1[QA], i2[QA];
    #pragma unroll
    for (int k = 0; k < QA; ++k) {
        v0[k] = v1[k] = v2[k] = CUDART_INF_F;
        i0[k] = i1[k] = i2[k] = 0;
    }

    const int jbase = s * SLICE;

    #pragma unroll 4
    for (int p = 0; p < SLICE / 2; ++p) {
        ulonglong2 A  = spair[2 * p + 0];   // xs, ys (packed point-pairs)
        ulonglong2 Bv = spair[2 * p + 1];   // zs, hs

        #pragma unroll
        for (int k = 0; k < QA; ++k) {
            unsigned long long sP = fma2(A.x, nx[k], Bv.y);
            sP = fma2(A.y, ny[k], sP);
            sP = fma2(Bv.x, nz[k], sP);
            float s0, s1;
            unpk2(sP, s0, s1);
            if (fminf(s0, s1) < v2[k]) {     // per-query gate, branchy inserts
                ins3(s0, jbase + 2 * p,     v0[k], v1[k], v2[k], i0[k], i1[k], i2[k]);
                ins3(s1, jbase + 2 * p + 1, v0[k], v1[k], v2[k], i0[k], i1[k], i2[k]);
            }
        }
    }

    #pragma unroll
    for (int k = 0; k < QA; ++k) {
        const int q = qbase + k * TPB_A;
        const size_t o = ((size_t)s * BATCH + b) * NUP + q;
        g_scrV[o] = make_float4(v0[k], v1[k], v2[k], 0.0f);
        g_scrI[o] = make_float4(__int_as_float(i0[k]), __int_as_float(i1[k]),
                                __int_as_float(i2[k]), 0.0f);
    }
}

// ====== Phase B: merge-once + 8 d-groups x 2 queries/thread, smem W, f32x2 ===
// QBLK=64: smaller per-block critical path, 36KB smem -> ~4 resident blocks/SM.
__global__ void __launch_bounds__(TPB_B, 4)
epilogue_kernel(const float* __restrict__ feature,
                const float* __restrict__ pos_up,
                const float* __restrict__ W,
                const float* __restrict__ bias,
                float* __restrict__ out)
{
    extern __shared__ float sm[];
    float* sW  = sm;                         // [4096]  row c = 64 floats
    float* sb  = sW + C * C;                 // [64]
    float* sWT = sb + C;                     // [64*4] w0,w1,w2,_
    float* sID = sWT + QBLK_B * 4;           // [64*4] i0,i1,i2,_ (bitcast int)
    float* snf = sID + QBLK_B * 4;           // [64*NFS]

    const int b    = blockIdx.y;
    const int tid  = threadIdx.x;
    const int w    = tid >> 5;               // d-group: outputs [8w, 8w+8)
    const int lane = tid & 31;
    const int qb   = blockIdx.x * QBLK_B;

    // ---- stage 1: threads 0-63 merge one query each; 64-255 stage W/b ----
    if (tid < QBLK_B) {
        const int q = qb + tid;
        float v0 = CUDART_INF_F, v1 = CUDART_INF_F, v2 = CUDART_INF_F;
        int   i0 = 0, i1 = 0, i2 = 0;
        #pragma unroll
        for (int s = 0; s < S; ++s) {
            const size_t o = ((size_t)s * BATCH + b) * NUP + q;
            float4 vv = g_scrV[o];
            float4 ii = g_scrI[o];
            ins3(vv.x, __float_as_int(ii.x), v0, v1, v2, i0, i1, i2);
            ins3(vv.y, __float_as_int(ii.y), v0, v1, v2, i0, i1, i2);
            ins3(vv.z, __float_as_int(ii.z), v0, v1, v2, i0, i1, i2);
        }
        const float* pu = pos_up + (size_t)(b * NUP + q) * 3;
        const float pux = pu[0], puy = pu[1], puz = pu[2];
        const float nu  = pux * pux + puy * puy + puz * puz;
        float w0 = 1.0f / (__fmaf_rn(2.0f, v0, nu) + 1e-6f);
        float w1 = 1.0f / (__fmaf_rn(2.0f, v1, nu) + 1e-6f);
        float w2 = 1.0f / (__fmaf_rn(2.0f, v2, nu) + 1e-6f);
        float inv = 1.0f / (w0 + w1 + w2);
        reinterpret_cast<float4*>(sWT)[tid] = make_float4(w0 * inv, w1 * inv, w2 * inv, 0.0f);
        reinterpret_cast<float4*>(sID)[tid] = make_float4(__int_as_float(i0), __int_as_float(i1),
                                                          __int_as_float(i2), 0.0f);
    } else {
        const int t = tid - QBLK_B;          // 0..191
        const float4* Wg = reinterpret_cast<const float4*>(W);
        float4*       Ws = reinterpret_cast<float4*>(sW);
        for (int i = t; i < C * C / 4; i += TPB_B - QBLK_B) Ws[i] = Wg[i];
        if (t < C / 4)
            reinterpret_cast<float4*>(sb)[t] = reinterpret_cast<const float4*>(bias)[t];
    }
    __syncthreads();

    // ---- stage 2: nf for channels [8w, 8w+8) of 2 queries -> padded smem ----
    #pragma unroll
    for (int k = 0; k < 2; ++k) {
        const int qloc = k * 32 + lane;
        float4 wt = reinterpret_cast<const float4*>(sWT)[qloc];
        float4 id = reinterpret_cast<const float4*>(sID)[qloc];
        const int i0 = __float_as_int(id.x);
        const int i1 = __float_as_int(id.y);
        const int i2 = __float_as_int(id.z);

        const float4* f0 = reinterpret_cast<const float4*>(feature + (size_t)(b * NPTS + i0) * C) + 2 * w;
        const float4* f1 = reinterpret_cast<const float4*>(feature + (size_t)(b * NPTS + i1) * C) + 2 * w;
        const float4* f2 = reinterpret_cast<const float4*>(feature + (size_t)(b * NPTS + i2) * C) + 2 * w;
        float4* dst = reinterpret_cast<float4*>(snf + qloc * NFS + 8 * w);
        #pragma unroll
        for (int i = 0; i < 2; ++i) {
            float4 a = __ldg(f0 + i);
            float4 e = __ldg(f1 + i);
            float4 g = __ldg(f2 + i);
            float4 nf;
            nf.x = __fmaf_rn(wt.x, a.x, __fmaf_rn(wt.y, e.x, wt.z * g.x));
            nf.y = __fmaf_rn(wt.x, a.y, __fmaf_rn(wt.y, e.y, wt.z * g.y));
            nf.z = __fmaf_rn(wt.x, a.z, __fmaf_rn(wt.y, e.z, wt.z * g.z));
            nf.w = __fmaf_rn(wt.x, a.w, __fmaf_rn(wt.y, e.w, wt.z * g.w));
            dst[i] = nf;
        }
    }
    __syncthreads();

    // ---- stage 3: GEMM, 2 queries x 8 outputs (4 packed d-pairs each) ----
    const ulonglong2* sW2 = reinterpret_cast<const ulonglong2*>(sW);  // row c = 16 u2

    unsigned long long acc2[2][4];
    {
        const unsigned long long* sb1 = reinterpret_cast<const unsigned long long*>(sb);
        unsigned long long b0 = sb1[4 * w + 0], b1 = sb1[4 * w + 1];
        unsigned long long b2 = sb1[4 * w + 2], b3 = sb1[4 * w + 3];
        #pragma unroll
        for (int k = 0; k < 2; ++k) {
            acc2[k][0] = b0; acc2[k][1] = b1; acc2[k][2] = b2; acc2[k][3] = b3;
        }
    }

    #pragma unroll 4
    for (int c4 = 0; c4 < 16; ++c4) {
        float4 nf4[2];
        #pragma unroll
        for (int k = 0; k < 2; ++k)
            nf4[k] = *reinterpret_cast<const float4*>(snf + (k * 32 + lane) * NFS + 4 * c4);

        #pragma unroll
        for (int kk = 0; kk < 4; ++kk) {
            const int c = 4 * c4 + kk;
            ulonglong2 wa = sW2[(size_t)c * 16 + 2 * w + 0];   // LDS.128 broadcast
            ulonglong2 wb = sW2[(size_t)c * 16 + 2 * w + 1];
            #pragma unroll
            for (int k = 0; k < 2; ++k) {
                const float nfv = kk == 0 ? nf4[k].x : kk == 1 ? nf4[k].y
                                 : kk == 2 ? nf4[k].z : nf4[k].w;
                const unsigned long long nf2 = pk2(nfv, nfv);
                acc2[k][0] = fma2(nf2, wa.x, acc2[k][0]);
                acc2[k][1] = fma2(nf2, wa.y, acc2[k][1]);
                acc2[k][2] = fma2(nf2, wb.x, acc2[k][2]);
                acc2[k][3] = fma2(nf2, wb.y, acc2[k][3]);
            }
        }
    }

    // ---- ReLU + store: each query's d-segment [8w, 8w+8) ----
    #pragma unroll
    for (int k = 0; k < 2; ++k) {
        const int q = qb + k * 32 + lane;
        float4* o4 = reinterpret_cast<float4*>(out + (size_t)(b * NUP + q) * C + 8 * w);
        float x0, x1, x2, x3;
        unpk2(acc2[k][0], x0, x1);
        unpk2(acc2[k][1], x2, x3);
        o4[0] = make_float4(fmaxf(x0, 0.0f), fmaxf(x1, 0.0f), fmaxf(x2, 0.0f), fmaxf(x3, 0.0f));
        unpk2(acc2[k][2], x0, x1);
        unpk2(acc2[k][3], x2, x3);
        o4[1] = make_float4(fmaxf(x0, 0.0f), fmaxf(x1, 0.0f), fmaxf(x2, 0.0f), fmaxf(x3, 0.0f));
    }
}

extern "C" void kernel_launch(void* const* d_in, const int* in_sizes, int n_in,
                              void* d_out, int out_size)
{
    const float* feature = (const float*)d_in[0];
    const float* pos     = (const float*)d_in[1];
    const float* pos_up  = (const float*)d_in[2];
    const float* W       = (const float*)d_in[3];
    const float* bias    = (const float*)d_in[4];
    float* out = (float*)d_out;

    cudaFuncSetAttribute(epilogue_kernel, cudaFuncAttributeMaxDynamicSharedMemorySize, SMEM_B);

    dim3 gridA(NUP / QTILE, S, BATCH);      // (64, 4, 4) = 1024 blocks
    knn_slice_kernel<<<gridA, TPB_A>>>(pos, pos_up);

    dim3 gridB(NUP / QBLK_B, BATCH);        // (256, 4) = 1024 blocks
    epilogue_kernel<<<gridB, TPB_B, SMEM_B>>>(feature, pos_up, W, bias, out);
}